// round 1
// baseline (speedup 1.0000x reference)
#include <cuda_runtime.h>

#define SEQ    2048
#define NBATCH 4
#define DMODEL 768
#define NHEAD  12
#define DHEAD  64
#define MROWS  (NBATCH * SEQ)   // 8192

// Scratch (device globals: allocation-free per harness rules)
__device__ float g_q[NBATCH * NHEAD * SEQ * DHEAD];
__device__ float g_k[NBATCH * NHEAD * SEQ * DHEAD];
__device__ float g_v[NBATCH * NHEAD * SEQ * DHEAD];
__device__ float g_ctx[MROWS * DMODEL];

// ---------------------------------------------------------------------------
// SGEMM: C[M,N] = A[M,K] * B[K,N], 128x128 tile, BK=8, 256 threads, 8x8/thread
// MODE 0: plain write to C.
// MODE 1: scatter QKV output into g_q/g_k/g_v head-major layout
//         [b, h, n, dh] = [4, 12, 2048, 64].
// ---------------------------------------------------------------------------
template <int MODE, int ND, int KD>
__global__ __launch_bounds__(256)
void sgemm128(const float* __restrict__ A, const float* __restrict__ Bm,
              float* __restrict__ C)
{
    __shared__ float As[8][128];
    __shared__ float Bs[8][128];

    const int tid  = threadIdx.x;
    const int m0   = blockIdx.y * 128;
    const int n0   = blockIdx.x * 128;
    const int ty   = tid >> 4;        // 0..15
    const int tx   = tid & 15;        // 0..15
    const int arow = tid >> 1;        // 0..127
    const int ac   = (tid & 1) * 4;   // 0 or 4
    const int brow = tid >> 5;        // 0..7
    const int bc   = (tid & 31) * 4;  // 0..124

    float acc[8][8];
#pragma unroll
    for (int i = 0; i < 8; i++)
#pragma unroll
        for (int j = 0; j < 8; j++) acc[i][j] = 0.0f;

    const float* Ap = A + (size_t)(m0 + arow) * KD + ac;
    const float* Bp = Bm + (size_t)brow * ND + n0 + bc;

    for (int k0 = 0; k0 < KD; k0 += 8) {
        float4 av = *(const float4*)(Ap + k0);
        float4 bv = *(const float4*)(Bp + (size_t)k0 * ND);
        __syncthreads();
        As[ac + 0][arow] = av.x;
        As[ac + 1][arow] = av.y;
        As[ac + 2][arow] = av.z;
        As[ac + 3][arow] = av.w;
        *(float4*)&Bs[brow][bc] = bv;
        __syncthreads();
#pragma unroll
        for (int kk = 0; kk < 8; kk++) {
            float a[8], b[8];
            *(float4*)&a[0] = *(const float4*)&As[kk][ty * 8];
            *(float4*)&a[4] = *(const float4*)&As[kk][ty * 8 + 4];
            *(float4*)&b[0] = *(const float4*)&Bs[kk][tx * 8];
            *(float4*)&b[4] = *(const float4*)&Bs[kk][tx * 8 + 4];
#pragma unroll
            for (int i = 0; i < 8; i++)
#pragma unroll
                for (int j = 0; j < 8; j++)
                    acc[i][j] += a[i] * b[j];
        }
    }

    if (MODE == 0) {
#pragma unroll
        for (int i = 0; i < 8; i++) {
            float* crow = C + (size_t)(m0 + ty * 8 + i) * ND + n0 + tx * 8;
            float4 v0 = make_float4(acc[i][0], acc[i][1], acc[i][2], acc[i][3]);
            float4 v1 = make_float4(acc[i][4], acc[i][5], acc[i][6], acc[i][7]);
            *(float4*)(crow)     = v0;
            *(float4*)(crow + 4) = v1;
        }
    } else {
        // Scatter into Q/K/V head-major buffers.
        const int jg    = n0 + tx * 8;         // global output column, mult of 8
        const int which = jg / DMODEL;         // 0=Q,1=K,2=V
        const int rem   = jg - which * DMODEL; // within-D column, mult of 8
        const int h     = rem >> 6;
        const int dh    = rem & 63;            // mult of 8, dh+7 < 64
        float* base = (which == 0) ? g_q : (which == 1) ? g_k : g_v;
#pragma unroll
        for (int i = 0; i < 8; i++) {
            const int m  = m0 + ty * 8 + i;
            const int b_ = m >> 11;            // / 2048
            const int n_ = m & (SEQ - 1);
            float* dst = base + (((size_t)(b_ * NHEAD + h) * SEQ + n_) * DHEAD + dh);
            float4 v0 = make_float4(acc[i][0], acc[i][1], acc[i][2], acc[i][3]);
            float4 v1 = make_float4(acc[i][4], acc[i][5], acc[i][6], acc[i][7]);
            *(float4*)(dst)     = v0;
            *(float4*)(dst + 4) = v1;
        }
    }
}

// ---------------------------------------------------------------------------
// Flash attention, causal. BM = BN = 64, DH = 64, 256 threads, 4x4 per thread.
// Qt, Kt stored d-major (transposed) in smem -> conflict-free LDS.128 in the
// S inner loop. Vs row-major (k-major). Ps padded to 68 cols.
// grid: (32 q-tiles, 48 b*h)
// ---------------------------------------------------------------------------
#define PS_LD 68
#define ATTN_SMEM_FLOATS (64 * 64 * 3 + 64 * PS_LD)
#define ATTN_SMEM_BYTES  (ATTN_SMEM_FLOATS * 4)

__global__ __launch_bounds__(256)
void attn_kernel()
{
    extern __shared__ float sm[];
    float* Qt = sm;                 // [64][64], Qt[d*64 + q]
    float* Kt = Qt + 64 * 64;       // [64][64], Kt[d*64 + k]
    float* Vs = Kt + 64 * 64;       // [64][64], Vs[k*64 + d]
    float* Ps = Vs + 64 * 64;       // [64][PS_LD], Ps[q*PS_LD + k]

    const int tid = threadIdx.x;
    const int qt  = blockIdx.x;     // 0..31
    const int bh  = blockIdx.y;     // 0..47
    const int q0  = qt * 64;

    const float* qp = g_q + (size_t)bh * SEQ * DHEAD;
    const float* kp = g_k + (size_t)bh * SEQ * DHEAD;
    const float* vp = g_v + (size_t)bh * SEQ * DHEAD;

    const int r  = tid >> 2;        // 0..63 (row for loads)
    const int cc = tid & 3;         // 0..3  (16-float chunk)
    const int ty = tid >> 4;        // 0..15
    const int tx = tid & 15;        // 0..15
    const int ty4 = ty * 4, tx4 = tx * 4;

    // Load Q tile transposed (once per CTA)
    {
        const float* src = qp + (size_t)(q0 + r) * DHEAD + cc * 16;
#pragma unroll
        for (int u = 0; u < 4; u++) {
            float4 v = *(const float4*)(src + u * 4);
            const int d = cc * 16 + u * 4;
            Qt[(d + 0) * 64 + r] = v.x;
            Qt[(d + 1) * 64 + r] = v.y;
            Qt[(d + 2) * 64 + r] = v.z;
            Qt[(d + 3) * 64 + r] = v.w;
        }
    }

    float m_i[4], l_i[4], o[4][4];
#pragma unroll
    for (int i = 0; i < 4; i++) {
        m_i[i] = -1e30f;
        l_i[i] = 0.0f;
#pragma unroll
        for (int j = 0; j < 4; j++) o[i][j] = 0.0f;
    }

    for (int t = 0; t <= qt; t++) {
        const int k0 = t * 64;
        __syncthreads();  // previous tile's PV reads of Vs/Ps complete; Qt visible (t=0)

        // Load K (transposed) and V tiles
        {
            const float* ksrc = kp + (size_t)(k0 + r) * DHEAD + cc * 16;
            const float* vsrc = vp + (size_t)(k0 + r) * DHEAD + cc * 16;
#pragma unroll
            for (int u = 0; u < 4; u++) {
                float4 kv = *(const float4*)(ksrc + u * 4);
                const int d = cc * 16 + u * 4;
                Kt[(d + 0) * 64 + r] = kv.x;
                Kt[(d + 1) * 64 + r] = kv.y;
                Kt[(d + 2) * 64 + r] = kv.z;
                Kt[(d + 3) * 64 + r] = kv.w;
                float4 vv = *(const float4*)(vsrc + u * 4);
                *(float4*)&Vs[r * 64 + d] = vv;
            }
        }
        __syncthreads();

        // S = (Q K^T) * 0.125
        float s[4][4];
#pragma unroll
        for (int i = 0; i < 4; i++)
#pragma unroll
            for (int j = 0; j < 4; j++) s[i][j] = 0.0f;

#pragma unroll 8
        for (int dd = 0; dd < 64; dd++) {
            float4 a = *(const float4*)&Qt[dd * 64 + ty4];
            float4 b = *(const float4*)&Kt[dd * 64 + tx4];
            const float av[4] = {a.x, a.y, a.z, a.w};
            const float bv[4] = {b.x, b.y, b.z, b.w};
#pragma unroll
            for (int i = 0; i < 4; i++)
#pragma unroll
                for (int j = 0; j < 4; j++)
                    s[i][j] += av[i] * bv[j];
        }
#pragma unroll
        for (int i = 0; i < 4; i++)
#pragma unroll
            for (int j = 0; j < 4; j++) s[i][j] *= 0.125f;

        // Causal mask (only the diagonal tile needs it)
        if (t == qt) {
#pragma unroll
            for (int i = 0; i < 4; i++)
#pragma unroll
                for (int j = 0; j < 4; j++)
                    if (k0 + tx4 + j > q0 + ty4 + i) s[i][j] = -1e30f;
        }

        // Online softmax (row reductions across the 16 tx lanes)
#pragma unroll
        for (int i = 0; i < 4; i++) {
            float mx = s[i][0];
#pragma unroll
            for (int j = 1; j < 4; j++) mx = fmaxf(mx, s[i][j]);
#pragma unroll
            for (int off = 8; off >= 1; off >>= 1)
                mx = fmaxf(mx, __shfl_xor_sync(0xffffffffu, mx, off));
            const float mnew = fmaxf(m_i[i], mx);
            const float corr = __expf(m_i[i] - mnew);
            float rs = 0.0f;
#pragma unroll
            for (int j = 0; j < 4; j++) {
                const float p = __expf(s[i][j] - mnew);
                s[i][j] = p;
                rs += p;
            }
#pragma unroll
            for (int off = 8; off >= 1; off >>= 1)
                rs += __shfl_xor_sync(0xffffffffu, rs, off);
            l_i[i] = l_i[i] * corr + rs;
            m_i[i] = mnew;
#pragma unroll
            for (int j = 0; j < 4; j++) o[i][j] *= corr;
        }

        // Stage P in shared
#pragma unroll
        for (int i = 0; i < 4; i++) {
            float4 pv = make_float4(s[i][0], s[i][1], s[i][2], s[i][3]);
            *(float4*)&Ps[(ty4 + i) * PS_LD + tx4] = pv;
        }
        __syncthreads();

        // O += P @ V
#pragma unroll 8
        for (int kk = 0; kk < 64; kk++) {
            float4 b = *(const float4*)&Vs[kk * 64 + tx4];
#pragma unroll
            for (int i = 0; i < 4; i++) {
                const float a = Ps[(ty4 + i) * PS_LD + kk];
                o[i][0] += a * b.x;
                o[i][1] += a * b.y;
                o[i][2] += a * b.z;
                o[i][3] += a * b.w;
            }
        }
    }

    // Normalize + write context in [b, n, (h,dh)] layout
    const int b_ = bh / NHEAD;
    const int h_ = bh - b_ * NHEAD;
#pragma unroll
    for (int i = 0; i < 4; i++) {
        const int qrow = q0 + ty4 + i;
        const float inv = 1.0f / l_i[i];
        float4 v = make_float4(o[i][0] * inv, o[i][1] * inv,
                               o[i][2] * inv, o[i][3] * inv);
        *(float4*)&g_ctx[(size_t)(b_ * SEQ + qrow) * DMODEL + h_ * DHEAD + tx4] = v;
    }
}

// ---------------------------------------------------------------------------
extern "C" void kernel_launch(void* const* d_in, const int* in_sizes, int n_in,
                              void* d_out, int out_size)
{
    const float* x     = (const float*)d_in[0];
    // d_in[1] = mask (int32 causal tril) — causality implemented directly
    const float* w_qkv = (const float*)d_in[2];
    const float* w_out = (const float*)d_in[3];
    float* out = (float*)d_out;

    void* ctx_ptr = nullptr;
    cudaGetSymbolAddress(&ctx_ptr, g_ctx);

    cudaFuncSetAttribute(attn_kernel,
                         cudaFuncAttributeMaxDynamicSharedMemorySize,
                         ATTN_SMEM_BYTES);

    // 1) QKV projection: [8192,768] x [768,2304] -> scattered Q/K/V
    sgemm128<1, 3 * DMODEL, DMODEL><<<dim3(18, 64), 256>>>(x, w_qkv, nullptr);

    // 2) Causal flash attention -> g_ctx [8192,768]
    attn_kernel<<<dim3(SEQ / 64, NBATCH * NHEAD), 256, ATTN_SMEM_BYTES>>>();

    // 3) Output projection: [8192,768] x [768,768] -> d_out
    sgemm128<0, DMODEL, DMODEL><<<dim3(6, 64), 256>>>((const float*)ctx_ptr,
                                                      w_out, out);
}

// round 3
// speedup vs baseline: 2.4496x; 2.4496x over previous
#include <cuda_runtime.h>
#include <cuda_bf16.h>

#define SEQ    2048
#define NBATCH 4
#define DMODEL 768
#define NHEAD  12
#define DHEAD  64
#define MROWS  (NBATCH * SEQ)   // 8192

typedef __nv_bfloat16 bf16;
typedef __nv_bfloat162 bf162;

// ---------------- device scratch ----------------
__device__ bf16 g_xh[MROWS * DMODEL];
__device__ bf16 g_xl[MROWS * DMODEL];
__device__ bf16 g_wqh[3 * DMODEL * DMODEL];   // transposed [N][K]
__device__ bf16 g_wql[3 * DMODEL * DMODEL];
__device__ bf16 g_woh[DMODEL * DMODEL];       // transposed [N][K]
__device__ bf16 g_wol[DMODEL * DMODEL];
__device__ bf16 g_qh[NBATCH * NHEAD * SEQ * DHEAD];
__device__ bf16 g_ql[NBATCH * NHEAD * SEQ * DHEAD];
__device__ bf16 g_kh[NBATCH * NHEAD * SEQ * DHEAD];
__device__ bf16 g_kl[NBATCH * NHEAD * SEQ * DHEAD];
__device__ bf16 g_vh[NBATCH * NHEAD * SEQ * DHEAD];
__device__ bf16 g_vl[NBATCH * NHEAD * SEQ * DHEAD];
__device__ bf16 g_ch[MROWS * DMODEL];
__device__ bf16 g_cl[MROWS * DMODEL];

// ---------------- helpers ----------------
__device__ __forceinline__ unsigned smem_u32(const void* p) {
    unsigned a;
    asm("{ .reg .u64 t; cvta.to.shared.u64 t, %1; cvt.u32.u64 %0, t; }"
        : "=r"(a) : "l"(p));
    return a;
}
__device__ __forceinline__ void ldsm_x4(unsigned r[4], unsigned addr) {
    asm volatile("ldmatrix.sync.aligned.m8n8.x4.shared.b16 {%0,%1,%2,%3}, [%4];"
                 : "=r"(r[0]), "=r"(r[1]), "=r"(r[2]), "=r"(r[3]) : "r"(addr));
}
__device__ __forceinline__ void ldsm_x4_t(unsigned r[4], unsigned addr) {
    asm volatile("ldmatrix.sync.aligned.m8n8.x4.trans.shared.b16 {%0,%1,%2,%3}, [%4];"
                 : "=r"(r[0]), "=r"(r[1]), "=r"(r[2]), "=r"(r[3]) : "r"(addr));
}
__device__ __forceinline__ void mma16816(float c[4], const unsigned a[4],
                                         unsigned b0, unsigned b1) {
    asm volatile(
        "mma.sync.aligned.m16n8k16.row.col.f32.bf16.bf16.f32 "
        "{%0,%1,%2,%3}, {%4,%5,%6,%7}, {%8,%9}, {%0,%1,%2,%3};"
        : "+f"(c[0]), "+f"(c[1]), "+f"(c[2]), "+f"(c[3])
        : "r"(a[0]), "r"(a[1]), "r"(a[2]), "r"(a[3]), "r"(b0), "r"(b1));
}
__device__ __forceinline__ unsigned pack_hi(float a, float b) {
    bf162 t;
    t.x = __float2bfloat16(a);
    t.y = __float2bfloat16(b);
    return *(unsigned*)&t;
}
__device__ __forceinline__ unsigned pack_lo(float a, float b, unsigned hi) {
    bf162 h = *(bf162*)&hi;
    bf162 t;
    t.x = __float2bfloat16(a - __bfloat162float(h.x));
    t.y = __float2bfloat16(b - __bfloat162float(h.y));
    return *(unsigned*)&t;
}

// ---------------------------------------------------------------------------
// HMMA GEMM: C[M,N] = A[M,K] * B[N,K]^T, bf16x3. CTA 128x128, BK=64, 256 thr.
// 8 warps, each 64x32 (wm = wid&1 row-block, wn = wid>>1 col-block).
// MODE 0: fp32 C row-major [M][ND]. MODE 1: hi/lo bf16 scatter to q/k/v.
// ---------------------------------------------------------------------------
#define GLD 72
#define GEMM_SMEM (4 * 128 * GLD * 2)

template <int MODE, int ND>
__global__ __launch_bounds__(256)
void mma_gemm(const bf16* __restrict__ Ah, const bf16* __restrict__ Al,
              const bf16* __restrict__ Bh, const bf16* __restrict__ Bl,
              float* __restrict__ C)
{
    constexpr int KD = DMODEL;
    extern __shared__ bf16 sm[];
    bf16* sAh = sm;
    bf16* sAl = sAh + 128 * GLD;
    bf16* sBh = sAl + 128 * GLD;
    bf16* sBl = sBh + 128 * GLD;

    const int tid = threadIdx.x, wid = tid >> 5, lane = tid & 31;
    const int m0 = blockIdx.y * 128, n0 = blockIdx.x * 128;
    const int rowbase = (wid & 1) * 64;
    const int colbase = (wid >> 1) * 32;

    float acc[4][4][4];
#pragma unroll
    for (int a = 0; a < 4; a++)
#pragma unroll
        for (int b = 0; b < 4; b++)
#pragma unroll
            for (int c = 0; c < 4; c++) acc[a][b][c] = 0.0f;

    for (int k0 = 0; k0 < KD; k0 += 64) {
        __syncthreads();
#pragma unroll
        for (int rep = 0; rep < 4; rep++) {
            const int idx = tid + rep * 256;
            const int row = idx >> 3, ch = (idx & 7) * 8;
            const size_t ga = (size_t)(m0 + row) * KD + k0 + ch;
            const size_t gb = (size_t)(n0 + row) * KD + k0 + ch;
            *(uint4*)&sAh[row * GLD + ch] = *(const uint4*)&Ah[ga];
            *(uint4*)&sAl[row * GLD + ch] = *(const uint4*)&Al[ga];
            *(uint4*)&sBh[row * GLD + ch] = *(const uint4*)&Bh[gb];
            *(uint4*)&sBl[row * GLD + ch] = *(const uint4*)&Bl[gb];
        }
        __syncthreads();

#pragma unroll
        for (int ks = 0; ks < 4; ks++) {
            const int fc = ks * 16 + (lane >> 4) * 8;
            unsigned ah[4][4], al[4][4];
#pragma unroll
            for (int mi = 0; mi < 4; mi++) {
                const int r = rowbase + mi * 16 + (lane & 15);
                ldsm_x4(ah[mi], smem_u32(&sAh[r * GLD + fc]));
                ldsm_x4(al[mi], smem_u32(&sAl[r * GLD + fc]));
            }
            unsigned bh[2][4], bl[2][4];
#pragma unroll
            for (int g = 0; g < 2; g++) {
                const int r = colbase + g * 16 + (lane & 15);
                ldsm_x4(bh[g], smem_u32(&sBh[r * GLD + fc]));
                ldsm_x4(bl[g], smem_u32(&sBl[r * GLD + fc]));
            }
#pragma unroll
            for (int mi = 0; mi < 4; mi++)
#pragma unroll
                for (int nj = 0; nj < 4; nj++) {
                    const int g = nj >> 1, o = nj & 1;
                    mma16816(acc[mi][nj], ah[mi], bh[g][o], bh[g][o + 2]);
                    mma16816(acc[mi][nj], ah[mi], bl[g][o], bl[g][o + 2]);
                    mma16816(acc[mi][nj], al[mi], bh[g][o], bh[g][o + 2]);
                }
        }
    }

    const int r0 = lane >> 2, c0 = (lane & 3) * 2;
    if (MODE == 0) {
#pragma unroll
        for (int mi = 0; mi < 4; mi++)
#pragma unroll
            for (int nj = 0; nj < 4; nj++) {
                const int row = m0 + rowbase + mi * 16 + r0;
                const int col = n0 + colbase + nj * 8 + c0;
                float2 v0 = make_float2(acc[mi][nj][0], acc[mi][nj][1]);
                float2 v1 = make_float2(acc[mi][nj][2], acc[mi][nj][3]);
                *(float2*)&C[(size_t)row * ND + col] = v0;
                *(float2*)&C[(size_t)(row + 8) * ND + col] = v1;
            }
    } else {
#pragma unroll
        for (int nj = 0; nj < 4; nj++) {
            const int jg    = n0 + colbase + nj * 8;
            const int which = jg / DMODEL;
            const int rem   = jg - which * DMODEL;
            const int h     = rem >> 6;
            const int dh    = (rem & 63) + c0;
            bf16* dsth = (which == 0) ? g_qh : (which == 1) ? g_kh : g_vh;
            bf16* dstl = (which == 0) ? g_ql : (which == 1) ? g_kl : g_vl;
#pragma unroll
            for (int mi = 0; mi < 4; mi++) {
                const int m  = m0 + rowbase + mi * 16 + r0;
                const int b_ = m >> 11;
                const int n_ = m & (SEQ - 1);
                const size_t d0 =
                    ((size_t)(b_ * NHEAD + h) * SEQ + n_) * DHEAD + dh;
                unsigned h0 = pack_hi(acc[mi][nj][0], acc[mi][nj][1]);
                unsigned l0 = pack_lo(acc[mi][nj][0], acc[mi][nj][1], h0);
                *(unsigned*)&dsth[d0] = h0;
                *(unsigned*)&dstl[d0] = l0;
                const size_t d1 = d0 + 8 * DHEAD;
                unsigned h1 = pack_hi(acc[mi][nj][2], acc[mi][nj][3]);
                unsigned l1 = pack_lo(acc[mi][nj][2], acc[mi][nj][3], h1);
                *(unsigned*)&dsth[d1] = h1;
                *(unsigned*)&dstl[d1] = l1;
            }
        }
    }
}

// ---------------------------------------------------------------------------
// HMMA flash attention, causal. BM=BN=64, 128 threads (4 warps, m16 each).
// bf16x3 for QK^T and PV; P->A-frag register reuse; V via ldmatrix.trans.
// ---------------------------------------------------------------------------
#define ALD 72
#define ATTN_SMEM (6 * 64 * ALD * 2)

__global__ __launch_bounds__(128)
void attn_mma()
{
    extern __shared__ bf16 asm_[];
    bf16* sQh = asm_;
    bf16* sQl = sQh + 64 * ALD;
    bf16* sKh = sQl + 64 * ALD;
    bf16* sKl = sKh + 64 * ALD;
    bf16* sVh = sKl + 64 * ALD;
    bf16* sVl = sVh + 64 * ALD;

    const int tid = threadIdx.x, wid = tid >> 5, lane = tid & 31;
    const int qt = blockIdx.x, bh = blockIdx.y;
    const int q0 = qt * 64;
    const int mo = wid * 16;
    const int r0 = lane >> 2, c0 = (lane & 3) * 2;

    const size_t hb = (size_t)bh * SEQ * DHEAD;

    // Load Q tile hi/lo
#pragma unroll
    for (int rep = 0; rep < 4; rep++) {
        const int idx = tid + rep * 128;
        const int row = idx >> 3, ch = (idx & 7) * 8;
        const size_t g = hb + (size_t)(q0 + row) * DHEAD + ch;
        *(uint4*)&sQh[row * ALD + ch] = *(const uint4*)&g_qh[g];
        *(uint4*)&sQl[row * ALD + ch] = *(const uint4*)&g_ql[g];
    }
    __syncthreads();

    // Q fragments (persist across all k-tiles)
    unsigned aqh[4][4], aql[4][4];
#pragma unroll
    for (int ks = 0; ks < 4; ks++) {
        const int r = mo + (lane & 15);
        const int c = ks * 16 + (lane >> 4) * 8;
        ldsm_x4(aqh[ks], smem_u32(&sQh[r * ALD + c]));
        ldsm_x4(aql[ks], smem_u32(&sQl[r * ALD + c]));
    }

    float m_[2] = {-1e30f, -1e30f}, l_[2] = {0.0f, 0.0f};
    float o[8][4];
#pragma unroll
    for (int j = 0; j < 8; j++)
#pragma unroll
        for (int i = 0; i < 4; i++) o[j][i] = 0.0f;

    for (int t = 0; t <= qt; t++) {
        const int k0t = t * 64;
        __syncthreads();
#pragma unroll
        for (int rep = 0; rep < 4; rep++) {
            const int idx = tid + rep * 128;
            const int row = idx >> 3, ch = (idx & 7) * 8;
            const size_t g = hb + (size_t)(k0t + row) * DHEAD + ch;
            *(uint4*)&sKh[row * ALD + ch] = *(const uint4*)&g_kh[g];
            *(uint4*)&sKl[row * ALD + ch] = *(const uint4*)&g_kl[g];
            *(uint4*)&sVh[row * ALD + ch] = *(const uint4*)&g_vh[g];
            *(uint4*)&sVl[row * ALD + ch] = *(const uint4*)&g_vl[g];
        }
        __syncthreads();

        // S = Q K^T (bf16x3)
        float s[8][4];
#pragma unroll
        for (int j = 0; j < 8; j++)
#pragma unroll
            for (int i = 0; i < 4; i++) s[j][i] = 0.0f;

#pragma unroll
        for (int ks = 0; ks < 4; ks++) {
            const int fc = ks * 16 + (lane >> 4) * 8;
            unsigned kh[4][4], kl[4][4];
#pragma unroll
            for (int g = 0; g < 4; g++) {
                const int r = g * 16 + (lane & 15);
                ldsm_x4(kh[g], smem_u32(&sKh[r * ALD + fc]));
                ldsm_x4(kl[g], smem_u32(&sKl[r * ALD + fc]));
            }
#pragma unroll
            for (int nj = 0; nj < 8; nj++) {
                const int g = nj >> 1, oo = nj & 1;
                mma16816(s[nj], aqh[ks], kh[g][oo], kh[g][oo + 2]);
                mma16816(s[nj], aqh[ks], kl[g][oo], kl[g][oo + 2]);
                mma16816(s[nj], aql[ks], kh[g][oo], kh[g][oo + 2]);
            }
        }
#pragma unroll
        for (int j = 0; j < 8; j++)
#pragma unroll
            for (int i = 0; i < 4; i++) s[j][i] *= 0.125f;

        if (t == qt) {  // causal mask on diagonal tile
            const int rA = q0 + mo + r0, rB = rA + 8;
#pragma unroll
            for (int nj = 0; nj < 8; nj++) {
                const int cb = k0t + nj * 8 + c0;
                if (cb > rA)     s[nj][0] = -1e30f;
                if (cb + 1 > rA) s[nj][1] = -1e30f;
                if (cb > rB)     s[nj][2] = -1e30f;
                if (cb + 1 > rB) s[nj][3] = -1e30f;
            }
        }

        // online softmax, rows r0 (regs 0,1) and r0+8 (regs 2,3)
#pragma unroll
        for (int h = 0; h < 2; h++) {
            float mx = -1e30f;
#pragma unroll
            for (int nj = 0; nj < 8; nj++)
                mx = fmaxf(mx, fmaxf(s[nj][2 * h], s[nj][2 * h + 1]));
            mx = fmaxf(mx, __shfl_xor_sync(0xffffffffu, mx, 1));
            mx = fmaxf(mx, __shfl_xor_sync(0xffffffffu, mx, 2));
            const float mnew = fmaxf(m_[h], mx);
            const float corr = __expf(m_[h] - mnew);
            float rs = 0.0f;
#pragma unroll
            for (int nj = 0; nj < 8; nj++) {
                const float p0 = __expf(s[nj][2 * h] - mnew);
                const float p1 = __expf(s[nj][2 * h + 1] - mnew);
                s[nj][2 * h] = p0;
                s[nj][2 * h + 1] = p1;
                rs += p0 + p1;
            }
            rs += __shfl_xor_sync(0xffffffffu, rs, 1);
            rs += __shfl_xor_sync(0xffffffffu, rs, 2);
            l_[h] = l_[h] * corr + rs;
            m_[h] = mnew;
#pragma unroll
            for (int nj = 0; nj < 8; nj++) {
                o[nj][2 * h] *= corr;
                o[nj][2 * h + 1] *= corr;
            }
        }

        // P -> A fragments (hi/lo) in registers
        unsigned pah[4][4], pal[4][4];
#pragma unroll
        for (int ks = 0; ks < 4; ks++) {
            pah[ks][0] = pack_hi(s[2 * ks][0], s[2 * ks][1]);
            pal[ks][0] = pack_lo(s[2 * ks][0], s[2 * ks][1], pah[ks][0]);
            pah[ks][1] = pack_hi(s[2 * ks][2], s[2 * ks][3]);
            pal[ks][1] = pack_lo(s[2 * ks][2], s[2 * ks][3], pah[ks][1]);
            pah[ks][2] = pack_hi(s[2 * ks + 1][0], s[2 * ks + 1][1]);
            pal[ks][2] = pack_lo(s[2 * ks + 1][0], s[2 * ks + 1][1], pah[ks][2]);
            pah[ks][3] = pack_hi(s[2 * ks + 1][2], s[2 * ks + 1][3]);
            pal[ks][3] = pack_lo(s[2 * ks + 1][2], s[2 * ks + 1][3], pah[ks][3]);
        }

        // O += P V (bf16x3), V via ldmatrix.trans
#pragma unroll
        for (int ks = 0; ks < 4; ks++) {
            const int rr = 16 * ks + (lane & 7) + ((lane & 16) >> 1);
            const int ccb = ((lane >> 3) & 1) * 8;
            unsigned vh[4][4], vl[4][4];
#pragma unroll
            for (int g = 0; g < 4; g++) {
                const unsigned ad = smem_u32(&sVh[rr * ALD + g * 16 + ccb]);
                ldsm_x4_t(vh[g], ad);
                ldsm_x4_t(vl[g], smem_u32(&sVl[rr * ALD + g * 16 + ccb]));
            }
#pragma unroll
            for (int nj = 0; nj < 8; nj++) {
                const int g = nj >> 1, oo = nj & 1;
                mma16816(o[nj], pah[ks], vh[g][oo], vh[g][oo + 2]);
                mma16816(o[nj], pah[ks], vl[g][oo], vl[g][oo + 2]);
                mma16816(o[nj], pal[ks], vh[g][oo], vh[g][oo + 2]);
            }
        }
    }

    // normalize + write context hi/lo in [b, n, D] layout
    const int b_ = bh / NHEAD;
    const int h_ = bh - b_ * NHEAD;
    const float inv0 = 1.0f / l_[0];
    const float inv1 = 1.0f / l_[1];
    const size_t rbase =
        ((size_t)(b_ * SEQ + q0 + mo + r0)) * DMODEL + h_ * DHEAD;
#pragma unroll
    for (int nj = 0; nj < 8; nj++) {
        const int col = nj * 8 + c0;
        const float v0 = o[nj][0] * inv0, v1 = o[nj][1] * inv0;
        unsigned h0 = pack_hi(v0, v1);
        unsigned l0 = pack_lo(v0, v1, h0);
        *(unsigned*)&g_ch[rbase + col] = h0;
        *(unsigned*)&g_cl[rbase + col] = l0;
        const float v2 = o[nj][2] * inv1, v3 = o[nj][3] * inv1;
        unsigned h1 = pack_hi(v2, v3);
        unsigned l1 = pack_lo(v2, v3, h1);
        *(unsigned*)&g_ch[rbase + 8 * DMODEL + col] = h1;
        *(unsigned*)&g_cl[rbase + 8 * DMODEL + col] = l1;
    }
}

// ---------------- conversion kernels ----------------
__global__ void cvt_pair(const float* __restrict__ src, bf16* __restrict__ hi,
                         bf16* __restrict__ lo, int n)
{
    int i = blockIdx.x * blockDim.x + threadIdx.x;
    if (i < n) {
        float x = src[i];
        bf16 h = __float2bfloat16(x);
        hi[i] = h;
        lo[i] = __float2bfloat16(x - __bfloat162float(h));
    }
}
__global__ void cvt_tr(const float* __restrict__ src, bf16* __restrict__ hi,
                       bf16* __restrict__ lo, int K, int N)
{
    int i = blockIdx.x * blockDim.x + threadIdx.x;
    if (i < K * N) {
        int k = i / N, n = i - k * N;
        float x = src[i];
        bf16 h = __float2bfloat16(x);
        hi[(size_t)n * K + k] = h;
        lo[(size_t)n * K + k] = __float2bfloat16(x - __bfloat162float(h));
    }
}

// ---------------------------------------------------------------------------
extern "C" void kernel_launch(void* const* d_in, const int* in_sizes, int n_in,
                              void* d_out, int out_size)
{
    const float* x     = (const float*)d_in[0];
    const float* w_qkv = (const float*)d_in[2];
    const float* w_out = (const float*)d_in[3];
    float* out = (float*)d_out;

    void *p_xh, *p_xl, *p_wqh, *p_wql, *p_woh, *p_wol, *p_ch, *p_cl;
    cudaGetSymbolAddress(&p_xh, g_xh);   cudaGetSymbolAddress(&p_xl, g_xl);
    cudaGetSymbolAddress(&p_wqh, g_wqh); cudaGetSymbolAddress(&p_wql, g_wql);
    cudaGetSymbolAddress(&p_woh, g_woh); cudaGetSymbolAddress(&p_wol, g_wol);
    cudaGetSymbolAddress(&p_ch, g_ch);   cudaGetSymbolAddress(&p_cl, g_cl);

    cudaFuncSetAttribute(mma_gemm<1, 3 * DMODEL>,
                         cudaFuncAttributeMaxDynamicSharedMemorySize, GEMM_SMEM);
    cudaFuncSetAttribute(mma_gemm<0, DMODEL>,
                         cudaFuncAttributeMaxDynamicSharedMemorySize, GEMM_SMEM);
    cudaFuncSetAttribute(attn_mma,
                         cudaFuncAttributeMaxDynamicSharedMemorySize, ATTN_SMEM);

    const int nx = MROWS * DMODEL;
    cvt_pair<<<(nx + 255) / 256, 256>>>(x, (bf16*)p_xh, (bf16*)p_xl, nx);
    const int nwq = DMODEL * 3 * DMODEL;
    cvt_tr<<<(nwq + 255) / 256, 256>>>(w_qkv, (bf16*)p_wqh, (bf16*)p_wql,
                                       DMODEL, 3 * DMODEL);
    const int nwo = DMODEL * DMODEL;
    cvt_tr<<<(nwo + 255) / 256, 256>>>(w_out, (bf16*)p_woh, (bf16*)p_wol,
                                       DMODEL, DMODEL);

    // 1) QKV projection -> hi/lo bf16 Q/K/V (head-major)
    mma_gemm<1, 3 * DMODEL><<<dim3(18, 64), 256, GEMM_SMEM>>>(
        (const bf16*)p_xh, (const bf16*)p_xl,
        (const bf16*)p_wqh, (const bf16*)p_wql, nullptr);

    // 2) causal flash attention (HMMA) -> hi/lo bf16 context [b,n,D]
    attn_mma<<<dim3(SEQ / 64, NBATCH * NHEAD), 128, ATTN_SMEM>>>();

    // 3) output projection -> d_out (fp32)
    mma_gemm<0, DMODEL><<<dim3(6, 64), 256, GEMM_SMEM>>>(
        (const bf16*)p_ch, (const bf16*)p_cl,
        (const bf16*)p_woh, (const bf16*)p_wol, out);
}